// round 12
// baseline (speedup 1.0000x reference)
#include <cuda_runtime.h>

// RandomShiftsAug == integer shifted gather with edge clamp:
//   out[n,c,j,i] = x[n,c, clamp(j+sy-4,0,83), clamp(i+sx-4,0,83)]
//
// Established across R1-R11: traffic is pinned (~204MB/replay; L2 carveout is
// off-limits) and ~5.5 TB/s is the DRAM rate ceiling for this 36R/64W mix --
// three different front-ends (scalar-MLP, policy-hinted, cp.async.bulk) all
// saturate at the same rate. R12 removes the remaining *scheduling* overhead:
// persistent grid of 148 SMs x 8 blocks = 1184 blocks, each looping over ~4
// (n,c) slices (stride 1184), eliminating wave transitions and the low-
// utilization tail. Body = proven R5: lane-contiguous scalar, hoisted column
// clamp, 4x(7 loads + 7 stores) batching, default-policy loads, streaming
// stores, regs capped at 32.

#define N_   512
#define C_   9
#define H_   84
#define W_   84
#define PAD_ 4

#define SLICE    (H_ * W_)     // 7056
#define THREADS  252           // 3 rows x 84 cols
#define CHUNK    7
#define NCHUNK   4             // 28 rows per thread
#define NSLICES  (N_ * C_)     // 4608
#define GRID     1184          // 148 SMs x 8 resident blocks

__global__ __launch_bounds__(THREADS, 8) void random_shift_persist_kernel(
    const float* __restrict__ x,
    const int*   __restrict__ shift,
    float*       __restrict__ out)
{
    const int tid = threadIdx.x;
    const int i   = tid % W_;            // column, 0..83  (fixed per thread)
    const int j0  = tid / W_;            // starting row phase, 0..2

    for (int nc = blockIdx.x; nc < NSLICES; nc += GRID) {
        const int n  = nc / C_;
        const int sx = __ldg(&shift[2 * n + 0]) - PAD_;   // [-4, 4]
        const int sy = __ldg(&shift[2 * n + 1]) - PAD_;

        const int srcx = min(max(i + sx, 0), W_ - 1);     // column clamp, hoisted

        const float* __restrict__ src = x   + (long)nc * SLICE + srcx;
        float*       __restrict__ dst = out + (long)nc * SLICE + i;

        #pragma unroll
        for (int c = 0; c < NCHUNK; c++) {
            float v[CHUNK];
            #pragma unroll
            for (int k = 0; k < CHUNK; k++) {
                int j = j0 + 3 * (c * CHUNK + k);         // output row
                int srcy = min(max(j + sy, 0), H_ - 1);
                v[k] = src[srcy * W_];                    // default policy
            }
            #pragma unroll
            for (int k = 0; k < CHUNK; k++) {
                int j = j0 + 3 * (c * CHUNK + k);
                __stcs(dst + j * W_, v[k]);               // streaming store
            }
        }
    }
}

extern "C" void kernel_launch(void* const* d_in, const int* in_sizes, int n_in,
                              void* d_out, int out_size)
{
    const float* x     = (const float*)d_in[0];
    const int*   shift = (const int*)  d_in[1];
    float* out = (float*)d_out;

    random_shift_persist_kernel<<<GRID, THREADS>>>(x, shift, out);
}

// round 13
// speedup vs baseline: 1.0409x; 1.0409x over previous
#include <cuda_runtime.h>
#include <cstdint>

// RandomShiftsAug == integer shifted gather with edge clamp:
//   out[n,c,j,i] = x[n,c, clamp(j+sy-4,0,83), clamp(i+sx-4,0,83)]
//
// R13: BOTH global streams engine-driven.
//   read : cp.async.bulk global->smem (28224B per slice, mbarrier)
//   shift: resolved in-place in smem. 4 chunks of 21 rows; per chunk each
//          thread reads its 7 values to regs, barrier, writes back, barrier.
//          Chunk order ascending for sy>=0, descending for sy<0, so a write
//          never lands on a row a later chunk still needs (|sy|<=4 < 21).
//   write: cp.async.bulk shared->global bulk_group (engine-scheduled full-line
//          write bursts -- the 130MB write stream was register STG in every
//          prior round and is 64% of all DRAM traffic).

#define N_   512
#define C_   9
#define H_   84
#define W_   84
#define PAD_ 4

#define SLICE       (H_ * W_)          // 7056 floats
#define SLICE_BYTES (SLICE * 4)        // 28224 B
#define THREADS     252                // 84 cols x 3 row phases
#define CHUNK       7                  // rows per thread per chunk
#define NCHUNK      4                  // 4 chunks x 21-row bands

__device__ __forceinline__ uint32_t smem_u32(const void* p) {
    return (uint32_t)__cvta_generic_to_shared(p);
}

__global__ __launch_bounds__(THREADS, 8) void random_shift_tma2_kernel(
    const float* __restrict__ x,
    const int*   __restrict__ shift,
    float*       __restrict__ out)
{
    __shared__ alignas(128) float s[SLICE];
    __shared__ alignas(8)  uint64_t mbar;

    const int nc  = blockIdx.x;            // (n*C + c)
    const int n   = nc / C_;
    const int tid = threadIdx.x;

    const uint32_t bar = smem_u32(&mbar);

    if (tid == 0) {
        asm volatile("mbarrier.init.shared.b64 [%0], 1;" :: "r"(bar));
    }
    __syncthreads();

    if (tid == 0) {
        asm volatile("mbarrier.arrive.expect_tx.shared.b64 _, [%0], %1;"
                     :: "r"(bar), "r"((uint32_t)SLICE_BYTES) : "memory");
        asm volatile(
            "cp.async.bulk.shared::cluster.global.mbarrier::complete_tx::bytes "
            "[%0], [%1], %2, [%3];"
            :: "r"(smem_u32(s)), "l"(x + (long)nc * SLICE),
               "r"((uint32_t)SLICE_BYTES), "r"(bar)
            : "memory");
    }

    const int sx = __ldg(&shift[2 * n + 0]) - PAD_;   // [-4,4], block-uniform
    const int sy = __ldg(&shift[2 * n + 1]) - PAD_;

    const int i  = tid % W_;               // column, 0..83
    const int j0 = tid / W_;               // row phase, 0..2
    const int srcx = min(max(i + sx, 0), W_ - 1);

    // wait (acquire) for the bulk load
    asm volatile(
        "{\n\t"
        ".reg .pred P;\n\t"
        "WAIT_%=: \n\t"
        "mbarrier.try_wait.parity.acquire.cta.shared::cta.b64 P, [%0], 0, 0x989680;\n\t"
        "@P bra.uni DONE_%=;\n\t"
        "bra.uni WAIT_%=;\n\t"
        "DONE_%=: \n\t"
        "}"
        :: "r"(bar) : "memory");

    // ---- in-place shift, chunked; chunk order depends on sign of sy ----
    #pragma unroll
    for (int cc = 0; cc < NCHUNK; cc++) {
        const int c = (sy >= 0) ? cc : (NCHUNK - 1 - cc);
        const int jb = 21 * c + j0;                    // this thread's first row in band

        float v[CHUNK];
        #pragma unroll
        for (int k = 0; k < CHUNK; k++) {
            const int j    = jb + 3 * k;               // row in band [21c, 21c+21)
            const int srcy = min(max(j + sy, 0), H_ - 1);
            v[k] = s[srcy * W_ + srcx];
        }
        __syncthreads();                               // all reads before any write
        #pragma unroll
        for (int k = 0; k < CHUNK; k++) {
            const int j = jb + 3 * k;
            s[j * W_ + i] = v[k];
        }
        __syncthreads();                               // band committed before next chunk
    }

    // ---- bulk store smem -> global ----
    if (tid == 0) {
        asm volatile("fence.proxy.async;" ::: "memory");
        asm volatile(
            "cp.async.bulk.global.shared::cta.bulk_group [%0], [%1], %2;"
            :: "l"(out + (long)nc * SLICE), "r"(smem_u32(s)),
               "r"((uint32_t)SLICE_BYTES)
            : "memory");
        asm volatile("cp.async.bulk.commit_group;" ::: "memory");
        asm volatile("cp.async.bulk.wait_group 0;" ::: "memory");
    }
}

extern "C" void kernel_launch(void* const* d_in, const int* in_sizes, int n_in,
                              void* d_out, int out_size)
{
    const float* x     = (const float*)d_in[0];
    const int*   shift = (const int*)  d_in[1];
    float* out = (float*)d_out;

    random_shift_tma2_kernel<<<N_ * C_, THREADS>>>(x, shift, out);
}